// round 1
// baseline (speedup 1.0000x reference)
#include <cuda_runtime.h>

#define VN 48
#define VNN (48*48)
#define VNNN (48*48*48)
#define NB 8
#define NCH 32
#define NHID 64
#define NCLS 4
#define SP_EPS 1e-5f
#define TILE 8
#define TPD 6   // tiles per dim = 48/8

// Scratch: relu(conv1) activations, and per-(b,c) instance-norm stats
__device__ float g_actv[(size_t)NB * NHID * VNNN];
__device__ float g_mu[NB * NCH];
__device__ float g_rsig[NB * NCH];

// ---------------------------------------------------------------------------
// Kernel A: per-(b,c) mean / rsqrt(var+eps) over 48^3
// ---------------------------------------------------------------------------
__global__ void stats_kernel(const float* __restrict__ x) {
    int bc = blockIdx.x;  // 0..255
    const float4* xp = reinterpret_cast<const float4*>(x + (size_t)bc * VNNN);
    float s = 0.f, ss = 0.f;
    for (int i = threadIdx.x; i < VNNN / 4; i += blockDim.x) {
        float4 v = xp[i];
        s  += v.x + v.y + v.z + v.w;
        ss += v.x * v.x + v.y * v.y + v.z * v.z + v.w * v.w;
    }
    __shared__ float sh_s[8], sh_ss[8];
    #pragma unroll
    for (int o = 16; o; o >>= 1) {
        s  += __shfl_down_sync(0xffffffffu, s, o);
        ss += __shfl_down_sync(0xffffffffu, ss, o);
    }
    int w = threadIdx.x >> 5, l = threadIdx.x & 31;
    if (l == 0) { sh_s[w] = s; sh_ss[w] = ss; }
    __syncthreads();
    if (w == 0) {
        int nw = blockDim.x >> 5;
        s  = (l < nw) ? sh_s[l]  : 0.f;
        ss = (l < nw) ? sh_ss[l] : 0.f;
        #pragma unroll
        for (int o = 4; o; o >>= 1) {
            s  += __shfl_down_sync(0xffffffffu, s, o);
            ss += __shfl_down_sync(0xffffffffu, ss, o);
        }
        if (l == 0) {
            float mu  = s / (float)VNNN;
            float var = ss / (float)VNNN - mu * mu;
            g_mu[bc]   = mu;
            g_rsig[bc] = rsqrtf(var + SP_EPS);
        }
    }
}

// ---------------------------------------------------------------------------
// Kernel B: actv = relu(conv3d(x, Wshared[y]) + bshared[y])   32 -> 64 ch
// grid: (216 tiles, 4 oc-blocks of 16, 8 batch); 128 threads
// ---------------------------------------------------------------------------
__global__ __launch_bounds__(128)
void conv1_kernel(const float* __restrict__ x, const float* __restrict__ Ws,
                  const float* __restrict__ bs, const int* __restrict__ ycls) {
    __shared__ float s_in[8 * 1000];       // 8 in-ch, 10x10x10 halo tile
    __shared__ float s_w[16 * 8 * 27];     // 16 oc, 8 ic, 27 taps

    int t  = blockIdx.x;
    int tx = t % TPD, ty = (t / TPD) % TPD, tz = t / (TPD * TPD);
    int ocb = blockIdx.y;
    int b   = blockIdx.z;
    int cls = ycls[b];
    int tid = threadIdx.x;
    int lx = tid & 7, ly = (tid >> 3) & 7, zb = (tid >> 6) * 4;
    int x0 = tx * TILE, y0 = ty * TILE, z0 = tz * TILE;

    float acc[4][16];
    #pragma unroll
    for (int s = 0; s < 4; s++)
        #pragma unroll
        for (int o = 0; o < 16; o++) acc[s][o] = 0.f;

    const float* Wbase = Ws + ((size_t)cls * NHID + (size_t)ocb * 16) * (NCH * 27);

    for (int c0 = 0; c0 < NCH; c0 += 8) {
        const float* xb = x + ((size_t)b * NCH + c0) * VNNN;
        for (int i = tid; i < 8000; i += 128) {
            int ic = i / 1000; int r = i - ic * 1000;
            int lz = r / 100;  r -= lz * 100;
            int lyy = r / 10;  int lxx = r - lyy * 10;
            int gz = z0 + lz - 1, gy = y0 + lyy - 1, gx = x0 + lxx - 1;
            float v = 0.f;
            if ((unsigned)gz < VN && (unsigned)gy < VN && (unsigned)gx < VN)
                v = xb[(size_t)ic * VNNN + gz * VNN + gy * VN + gx];
            s_in[i] = v;
        }
        for (int i = tid; i < 16 * 8 * 27; i += 128) {
            int oc = i / (8 * 27); int r = i - oc * (8 * 27);
            int ic = r / 27; int k = r - ic * 27;
            s_w[i] = Wbase[(size_t)oc * (NCH * 27) + (size_t)(c0 + ic) * 27 + k];
        }
        __syncthreads();

        #pragma unroll 1
        for (int ic = 0; ic < 8; ++ic) {
            int ibase = ic * 1000 + zb * 100 + ly * 10 + lx;
            int wbase = ic * 27;
            #pragma unroll
            for (int kd = 0; kd < 3; ++kd)
                #pragma unroll
                for (int kh = 0; kh < 3; ++kh)
                    #pragma unroll
                    for (int kw = 0; kw < 3; ++kw) {
                        int k = (kd * 3 + kh) * 3 + kw;
                        float v[4];
                        #pragma unroll
                        for (int s = 0; s < 4; s++)
                            v[s] = s_in[ibase + (s + kd) * 100 + kh * 10 + kw];
                        #pragma unroll
                        for (int o = 0; o < 16; o++) {
                            float wv = s_w[o * 216 + wbase + k];
                            #pragma unroll
                            for (int s = 0; s < 4; s++)
                                acc[s][o] = fmaf(v[s], wv, acc[s][o]);
                        }
                    }
        }
        __syncthreads();
    }

    int gx = x0 + lx, gy = y0 + ly;
    #pragma unroll
    for (int o = 0; o < 16; o++) {
        int ocg = ocb * 16 + o;
        float bias = bs[cls * NHID + ocg];
        float* outp = g_actv + ((size_t)b * NHID + ocg) * VNNN + (size_t)gy * VN + gx;
        #pragma unroll
        for (int s = 0; s < 4; s++) {
            float v = acc[s][o] + bias;
            outp[(size_t)(z0 + zb + s) * VNN] = fmaxf(v, 0.f);
        }
    }
}

// ---------------------------------------------------------------------------
// Kernel C: gamma = conv(actv, Wg)+bg, beta = conv(actv, Wb)+bb  (64 -> 32)
//           out = (x - mu) * rsig * (1 + gamma) + beta
// grid: (216 tiles, 4 oc-blocks of 8, 8 batch); 128 threads
// ---------------------------------------------------------------------------
__global__ __launch_bounds__(128)
void conv2_kernel(const float* __restrict__ x,
                  const float* __restrict__ Wg, const float* __restrict__ bg,
                  const float* __restrict__ Wb, const float* __restrict__ bb,
                  const int* __restrict__ ycls, float* __restrict__ out) {
    __shared__ float s_in[8 * 1000];
    __shared__ float s_wg[8 * 8 * 27];
    __shared__ float s_wb[8 * 8 * 27];

    int t  = blockIdx.x;
    int tx = t % TPD, ty = (t / TPD) % TPD, tz = t / (TPD * TPD);
    int ocb = blockIdx.y;
    int b   = blockIdx.z;
    int cls = ycls[b];
    int tid = threadIdx.x;
    int lx = tid & 7, ly = (tid >> 3) & 7, zb = (tid >> 6) * 4;
    int x0 = tx * TILE, y0 = ty * TILE, z0 = tz * TILE;

    float accg[4][8], accb[4][8];
    #pragma unroll
    for (int s = 0; s < 4; s++)
        #pragma unroll
        for (int o = 0; o < 8; o++) { accg[s][o] = 0.f; accb[s][o] = 0.f; }

    const float* Wgb = Wg + ((size_t)cls * NCH + (size_t)ocb * 8) * (NHID * 27);
    const float* Wbb = Wb + ((size_t)cls * NCH + (size_t)ocb * 8) * (NHID * 27);

    for (int c0 = 0; c0 < NHID; c0 += 8) {
        const float* ab = g_actv + ((size_t)b * NHID + c0) * VNNN;
        for (int i = tid; i < 8000; i += 128) {
            int ic = i / 1000; int r = i - ic * 1000;
            int lz = r / 100;  r -= lz * 100;
            int lyy = r / 10;  int lxx = r - lyy * 10;
            int gz = z0 + lz - 1, gy = y0 + lyy - 1, gx = x0 + lxx - 1;
            float v = 0.f;
            if ((unsigned)gz < VN && (unsigned)gy < VN && (unsigned)gx < VN)
                v = ab[(size_t)ic * VNNN + gz * VNN + gy * VN + gx];
            s_in[i] = v;
        }
        for (int i = tid; i < 8 * 8 * 27; i += 128) {
            int oc = i / (8 * 27); int r = i - oc * (8 * 27);
            int ic = r / 27; int k = r - ic * 27;
            size_t goff = (size_t)oc * (NHID * 27) + (size_t)(c0 + ic) * 27 + k;
            s_wg[i] = Wgb[goff];
            s_wb[i] = Wbb[goff];
        }
        __syncthreads();

        #pragma unroll 1
        for (int ic = 0; ic < 8; ++ic) {
            int ibase = ic * 1000 + zb * 100 + ly * 10 + lx;
            int wbase = ic * 27;
            #pragma unroll
            for (int kd = 0; kd < 3; ++kd)
                #pragma unroll
                for (int kh = 0; kh < 3; ++kh)
                    #pragma unroll
                    for (int kw = 0; kw < 3; ++kw) {
                        int k = (kd * 3 + kh) * 3 + kw;
                        float v[4];
                        #pragma unroll
                        for (int s = 0; s < 4; s++)
                            v[s] = s_in[ibase + (s + kd) * 100 + kh * 10 + kw];
                        #pragma unroll
                        for (int o = 0; o < 8; o++) {
                            float wg = s_wg[o * 216 + wbase + k];
                            float wb = s_wb[o * 216 + wbase + k];
                            #pragma unroll
                            for (int s = 0; s < 4; s++) {
                                accg[s][o] = fmaf(v[s], wg, accg[s][o]);
                                accb[s][o] = fmaf(v[s], wb, accb[s][o]);
                            }
                        }
                    }
        }
        __syncthreads();
    }

    int gx = x0 + lx, gy = y0 + ly;
    #pragma unroll
    for (int o = 0; o < 8; o++) {
        int ocg = ocb * 8 + o;
        float bgv = bg[cls * NCH + ocg];
        float bbv = bb[cls * NCH + ocg];
        float mu  = g_mu[b * NCH + ocg];
        float rs  = g_rsig[b * NCH + ocg];
        const float* xp = x + ((size_t)b * NCH + ocg) * VNNN + (size_t)gy * VN + gx;
        float* op = out + ((size_t)b * NCH + ocg) * VNNN + (size_t)gy * VN + gx;
        #pragma unroll
        for (int s = 0; s < 4; s++) {
            size_t zoff = (size_t)(z0 + zb + s) * VNN;
            float gamma = accg[s][o] + bgv;
            float beta  = accb[s][o] + bbv;
            float xv = xp[zoff];
            op[zoff] = (xv - mu) * rs * (1.f + gamma) + beta;
        }
    }
}

// ---------------------------------------------------------------------------
extern "C" void kernel_launch(void* const* d_in, const int* in_sizes, int n_in,
                              void* d_out, int out_size) {
    const float* x       = (const float*)d_in[0];
    const int*   y       = (const int*)d_in[1];
    const float* Wshared = (const float*)d_in[2];
    const float* bshared = (const float*)d_in[3];
    const float* Wgamma  = (const float*)d_in[4];
    const float* bgamma  = (const float*)d_in[5];
    const float* Wbeta   = (const float*)d_in[6];
    const float* bbeta   = (const float*)d_in[7];
    float* out = (float*)d_out;

    stats_kernel<<<NB * NCH, 256>>>(x);

    dim3 grid1(TPD * TPD * TPD, NHID / 16, NB);
    conv1_kernel<<<grid1, 128>>>(x, Wshared, bshared, y);

    dim3 grid2(TPD * TPD * TPD, NCH / 8, NB);
    conv2_kernel<<<grid2, 128>>>(x, Wgamma, bgamma, Wbeta, bbeta, y, out);
}